// round 11
// baseline (speedup 1.0000x reference)
#include <cuda_runtime.h>

// Reference semantics after dead-code elimination:
//   r  = eye(3)                       (unconditional overwrite in reference)
//   tb = -mean(mkpts0, axis=1)        ( = -r @ src_mean with r = I )
// Output: 12 floats = [r row-major (9), tb (3)]; identity 1s at flat 0,4,8.
//
// Launch-overhead-bound (96 KB read = ~4 ns HBM; kernel dur = T_ovh ramp +
// one memory round trip + ~100 cyc tail). Shape sweep: TPB=1024 -> 3.84-4.35,
// TPB=256 -> 4.10, grid=1 -> 4.58. This round samples the last untried point:
// grid=3, TPB=512 (4 float4/thread, 16 warps -> narrower barrier, shorter fold).

#define ROWLEN   8192
#define TPB      512
#define NWARPS   (TPB / 32)          // 16
#define LD       (ROWLEN / 4 / TPB)  // 4 float4 per thread
#define INV_NEG  (-1.0f / 8192.0f)   // exact: power-of-two divisor

__global__ void __launch_bounds__(TPB, 1)
svdhead_kernel(const float* __restrict__ mkpts0, float* __restrict__ out) {
    const int b = blockIdx.x;       // row 0..2
    const int t = threadIdx.x;

    // Block 0 writes the 3x3 identity (1s at flat indices 0, 4, 8).
    if (b == 0 && t < 3) {
        if (t == 0) reinterpret_cast<float4*>(out)[0] = make_float4(1.f, 0.f, 0.f, 0.f);
        if (t == 1) reinterpret_cast<float4*>(out)[1] = make_float4(1.f, 0.f, 0.f, 0.f);
        if (t == 2) out[8] = 1.0f;
    }

    // 2048 float4 per row; 512 threads x 4 fully-unrolled LDG.128 each,
    // all issued back-to-back -> one memory round trip block-wide.
    const float4* row4 = reinterpret_cast<const float4*>(mkpts0)
                       + (size_t)b * (ROWLEN / 4) + t;
    float4 v[LD];
    #pragma unroll
    for (int i = 0; i < LD; i++) v[i] = row4[i * TPB];

    float p[LD];
    #pragma unroll
    for (int i = 0; i < LD; i++) p[i] = (v[i].x + v[i].y) + (v[i].z + v[i].w);
    float sum = (p[0] + p[1]) + (p[2] + p[3]);

    // Warp tree reduce: 5 shfl.
    #pragma unroll
    for (int off = 16; off > 0; off >>= 1)
        sum += __shfl_xor_sync(0xFFFFFFFFu, sum, off);

    __shared__ float warp_sums[NWARPS];
    if ((t & 31) == 0) warp_sums[t >> 5] = sum;
    __syncthreads();

    // Final fold: lanes 0-3 each grab 4 contiguous warp sums with one
    // conflict-free LDS.128, pairwise-add, then a 2-deep shfl tree.
    if (t < 4) {
        float4 w = reinterpret_cast<const float4*>(warp_sums)[t];
        float s = (w.x + w.y) + (w.z + w.w);
        #pragma unroll
        for (int off = 2; off > 0; off >>= 1)
            s += __shfl_xor_sync(0x0000000Fu, s, off);
        if (t == 0)
            out[9 + b] = s * INV_NEG;
    }
}

extern "C" void kernel_launch(void* const* d_in, const int* in_sizes, int n_in,
                              void* d_out, int out_size) {
    const float* mkpts0 = (const float*)d_in[0];
    float* out = (float*)d_out;
    svdhead_kernel<<<3, TPB>>>(mkpts0, out);
}